// round 1
// baseline (speedup 1.0000x reference)
#include <cuda_runtime.h>

// Izhikevich neuron simulation on GB300.
// input:  [32, 2000, 512] fp32 currents
// output: concat(spikes, voltages, recovery), each [32, 2000, 512] fp32
//
// One thread per (batch, neuron) sequence; sequential over 2000 timesteps.
// 512 CTAs x 32 threads = 16384 threads; lanes map to consecutive neurons
// so every global access is a fully-coalesced 128B line.

#define BATCH    32
#define NSTEPS   2000
#define NNEUR    512
#define PLANE    (NSTEPS * NNEUR)        // 1,024,000 elements per batch
#define NTOT     (BATCH * PLANE)         // 32,768,000 elements per output

__device__ __forceinline__ void izh_step(float& v, float& u, float i_t,
                                         float* __restrict__ sp,
                                         float* __restrict__ vp,
                                         float* __restrict__ up)
{
    // dv/du computed from OLD v,u (matches reference order)
    float dv = (0.04f * v * v + 5.0f * v + 140.0f - u + i_t) * 0.5f;   // * DT
    float du = (0.02f * (0.2f * v - u)) * 0.5f;                        // A*(B*v-u)*DT
    v = v + dv;
    u = u + du;
    bool  fired = (v >= 30.0f);
    float s = fired ? 1.0f : 0.0f;
    v = fired ? -65.0f : v;      // reset to C
    u = fired ? u + 8.0f : u;    // += D
    *sp = s;
    *vp = v;
    *up = u;
}

__global__ __launch_bounds__(32, 32)
void izhikevich_kernel(const float* __restrict__ in,
                       float* __restrict__ out_s,
                       float* __restrict__ out_v,
                       float* __restrict__ out_u)
{
    int tid = blockIdx.x * 32 + threadIdx.x;     // 0 .. 16383
    int b   = tid >> 9;                          // / 512
    int n   = tid & 511;                         // % 512

    const float* __restrict__ ip = in    + b * PLANE + n;
    float* __restrict__ sp       = out_s + b * PLANE + n;
    float* __restrict__ vp       = out_v + b * PLANE + n;
    float* __restrict__ up       = out_u + b * PLANE + n;

    float v = -65.0f;
    float u = -13.0f;   // B * C = 0.2 * -65

    // Unroll by 4: front-batched independent loads give MLP=4 per warp.
    #pragma unroll 1
    for (int t = 0; t < NSTEPS; t += 4) {
        float i0 = ip[0 * NNEUR];
        float i1 = ip[1 * NNEUR];
        float i2 = ip[2 * NNEUR];
        float i3 = ip[3 * NNEUR];

        izh_step(v, u, i0, sp + 0 * NNEUR, vp + 0 * NNEUR, up + 0 * NNEUR);
        izh_step(v, u, i1, sp + 1 * NNEUR, vp + 1 * NNEUR, up + 1 * NNEUR);
        izh_step(v, u, i2, sp + 2 * NNEUR, vp + 2 * NNEUR, up + 2 * NNEUR);
        izh_step(v, u, i3, sp + 3 * NNEUR, vp + 3 * NNEUR, up + 3 * NNEUR);

        ip += 4 * NNEUR;
        sp += 4 * NNEUR;
        vp += 4 * NNEUR;
        up += 4 * NNEUR;
    }
}

extern "C" void kernel_launch(void* const* d_in, const int* in_sizes, int n_in,
                              void* d_out, int out_size)
{
    const float* in = (const float*)d_in[0];
    float* out      = (float*)d_out;

    float* out_s = out;             // spikes
    float* out_v = out + NTOT;      // voltages
    float* out_u = out + 2 * NTOT;  // recovery

    izhikevich_kernel<<<512, 32>>>(in, out_s, out_v, out_u);
}

// round 2
// speedup vs baseline: 2.5065x; 2.5065x over previous
#include <cuda_runtime.h>

// Izhikevich neuron simulation on GB300 — round 2.
// input:  [32, 2000, 512] fp32 currents
// output: concat(spikes, voltages, recovery), each [32, 2000, 512] fp32
//
// One thread per (batch, neuron) sequence (16384 threads). Only ~0.86 warps
// per SMSP are resident, so DRAM latency must be hidden WITHIN the thread:
// unroll time by 16 and software-pipeline the input loads one chunk ahead.

#define BATCH    32
#define NSTEPS   2000
#define NNEUR    512
#define PLANE    (NSTEPS * NNEUR)
#define NTOT     (BATCH * PLANE)
#define UNROLL   16
#define NCHUNKS  (NSTEPS / UNROLL)       // 125

__device__ __forceinline__ void izh_step(float& v, float& u, float i_t,
                                         float* __restrict__ sp,
                                         float* __restrict__ vp,
                                         float* __restrict__ up)
{
    // dv/du from OLD v,u — matches the reference association order.
    float dv = (0.04f * v * v + 5.0f * v + 140.0f - u + i_t) * 0.5f;   // * DT
    float du = (0.02f * (0.2f * v - u)) * 0.5f;                        // A*(B*v-u)*DT
    v = v + dv;
    u = u + du;
    bool  fired = (v >= 30.0f);
    float s = fired ? 1.0f : 0.0f;
    v = fired ? -65.0f : v;      // reset to C
    u = fired ? u + 8.0f : u;    // += D
    __stcs(sp, s);               // streaming stores: write-once, bypass-ish L2 policy
    __stcs(vp, v);
    __stcs(up, u);
}

__global__ __launch_bounds__(32, 32)
void izhikevich_kernel(const float* __restrict__ in,
                       float* __restrict__ out_s,
                       float* __restrict__ out_v,
                       float* __restrict__ out_u)
{
    int tid = blockIdx.x * 32 + threadIdx.x;     // 0 .. 16383
    int b   = tid >> 9;
    int n   = tid & 511;

    const float* __restrict__ ip = in    + b * PLANE + n;
    float* __restrict__ sp       = out_s + b * PLANE + n;
    float* __restrict__ vp       = out_v + b * PLANE + n;
    float* __restrict__ up       = out_u + b * PLANE + n;

    float v = -65.0f;
    float u = -13.0f;   // B * C

    float cur[UNROLL];

    // Prologue: load chunk 0.
    #pragma unroll
    for (int j = 0; j < UNROLL; ++j)
        cur[j] = __ldcs(ip + j * NNEUR);
    ip += UNROLL * NNEUR;

    // Steady state: prefetch chunk c+1 while computing chunk c.
    #pragma unroll 1
    for (int c = 0; c < NCHUNKS - 1; ++c) {
        float nxt[UNROLL];
        #pragma unroll
        for (int j = 0; j < UNROLL; ++j)
            nxt[j] = __ldcs(ip + j * NNEUR);
        ip += UNROLL * NNEUR;

        #pragma unroll
        for (int j = 0; j < UNROLL; ++j)
            izh_step(v, u, cur[j], sp + j * NNEUR, vp + j * NNEUR, up + j * NNEUR);

        sp += UNROLL * NNEUR;
        vp += UNROLL * NNEUR;
        up += UNROLL * NNEUR;

        #pragma unroll
        for (int j = 0; j < UNROLL; ++j)
            cur[j] = nxt[j];
    }

    // Epilogue: last chunk.
    #pragma unroll
    for (int j = 0; j < UNROLL; ++j)
        izh_step(v, u, cur[j], sp + j * NNEUR, vp + j * NNEUR, up + j * NNEUR);
}

extern "C" void kernel_launch(void* const* d_in, const int* in_sizes, int n_in,
                              void* d_out, int out_size)
{
    const float* in = (const float*)d_in[0];
    float* out      = (float*)d_out;

    float* out_s = out;
    float* out_v = out + NTOT;
    float* out_u = out + 2 * NTOT;

    izhikevich_kernel<<<512, 32>>>(in, out_s, out_v, out_u);
}